// round 3
// baseline (speedup 1.0000x reference)
#include <cuda_runtime.h>
#include <cstdint>

#define FULL_MASK 0xFFFFFFFFu

// ---------------- problem constants ----------------
// B=8, I=16, C=256
// levels: H/W = 128,64,32,16 ; P = 16384,4096,1024,256
// scribbles: (8,16,512,512)
// resize: scale S={4,8,16,32}; both bilinear weights exactly 0.5, taps at
// S/2-1 and S/2 in each dim  -> first tap offset so={1,3,7,15}
#define MTOT 21760   // 16384+4096+1024+256 pixels per batch across levels

// ---------------- scratch (device globals; no allocation) ----------------
static __device__ float               d_s[4 * 8 * 16 * 256];     // per-level sums
static __device__ int                 d_cnt[4 * 8 * 16];         // per-level fg counts
static __device__ unsigned long long  d_key[4 * 8 * 16];         // argmax keys
static __device__ unsigned long long  d_mask[(8 * MTOT) / 4];    // bit-packed masks (uint16/pixel)

#define ADD2(d, a, b) \
    asm("add.rn.f32x2 %0, %1, %2;" : "=l"(d) : "l"(a), "l"(b))

// ---------------- kernel 0: zero scratch ----------------
__global__ void k_init() {
    int g = blockIdx.x * 256 + threadIdx.x;
    if (g < 4 * 8 * 16 * 256) d_s[g] = 0.0f;
    if (g < 4 * 8 * 16) { d_cnt[g] = 0; d_key[g] = 0ull; }
}

// ---------------- kernel 1: masks + counts + argmax ----------------
// 170 blocks x 256 threads. Each warp handles one 256-pixel tile for HALF of
// the 16 instances (8 each), writing its byte of the uint16 mask word.
__global__ void __launch_bounds__(256) k_mask(const float* __restrict__ scr) {
    const int warp = threadIdx.x >> 5;
    const int lane = threadIdx.x & 31;
    const int gw   = blockIdx.x * 8 + warp;   // 0..1359
    const int tile = gw >> 1;                 // 0..679
    const int ih   = gw & 1;                  // instance half (0: i0-7, 1: i8-15)
    const int wb   = tile * 256;              // global pixel base

    const int b = wb / MTOT;
    const int r = wb - b * MTOT;

    int lvl, loff, lw, ls, so;
    if (r < 16384)      { lvl = 0; loff = 0;     lw = 7; ls = 2; so = 1;  }
    else if (r < 20480) { lvl = 1; loff = 16384; lw = 6; ls = 3; so = 3;  }
    else if (r < 21504) { lvl = 2; loff = 20480; lw = 5; ls = 4; so = 7;  }
    else                { lvl = 3; loff = 21504; lw = 4; ls = 5; so = 15; }

    const int p0 = r - loff;
    const float* sbase = scr + (size_t)(b * 16 + ih * 8) * 262144;

    unsigned long long best[8];
#pragma unroll
    for (int i = 0; i < 8; ++i) best[i] = 0ull;
    unsigned cpack = 0u;  // 8 x 4-bit counters (max 8 each)

    unsigned char* mb = reinterpret_cast<unsigned char*>(d_mask);

#pragma unroll
    for (int k = 0; k < 8; ++k) {
        const int p  = p0 + k * 32 + lane;
        const int y  = p >> lw;
        const int x  = p & ((1 << lw) - 1);
        unsigned mask = 0u;

        if (lvl == 0) {
            // taps 4x+1, 4x+2 both live in aligned float4[x] of rows 4y+1, 4y+2
            const float* rp = sbase + (((y << 2) + 1) * 512 + (x << 2));
#pragma unroll
            for (int i = 0; i < 8; ++i) {
                const float4 q0 = *reinterpret_cast<const float4*>(rp + i * 262144);
                const float4 q1 = *reinterpret_cast<const float4*>(rp + i * 262144 + 512);
                float t0 = 0.5f * (q0.y + q1.y);
                float t1 = 0.5f * (q0.z + q1.z);
                float m  = 0.5f * (t0 + t1);

                unsigned bit = (m > 0.5f) ? 1u : 0u;
                mask  |= bit << i;
                cpack += bit << (4 * i);

                unsigned long long key =
                    ((unsigned long long)__float_as_uint(m) << 32) |
                    (unsigned long long)(0xFFFFFFFFu - (unsigned)p);
                if (key > best[i]) best[i] = key;
            }
        } else {
            const int y0 = (y << ls) + so;
            const int x0 = (x << ls) + so;
            const float* sp0 = sbase + y0 * 512 + x0;
#pragma unroll
            for (int i = 0; i < 8; ++i) {
                const float* sp = sp0 + i * 262144;
                float va = sp[0];
                float vb = sp[1];
                float vc = sp[512];
                float vd = sp[513];
                float t0 = 0.5f * (va + vc);
                float t1 = 0.5f * (vb + vd);
                float m  = 0.5f * (t0 + t1);

                unsigned bit = (m > 0.5f) ? 1u : 0u;
                mask  |= bit << i;
                cpack += bit << (4 * i);

                unsigned long long key =
                    ((unsigned long long)__float_as_uint(m) << 32) |
                    (unsigned long long)(0xFFFFFFFFu - (unsigned)p);
                if (key > best[i]) best[i] = key;
            }
        }
        mb[2 * (wb + k * 32 + lane) + ih] = (unsigned char)mask;
    }

    const int base = (lvl * 8 + b) * 16 + ih * 8;
#pragma unroll
    for (int i = 0; i < 8; ++i) {
        int c   = (int)((cpack >> (4 * i)) & 15u);
        int tot = __reduce_add_sync(FULL_MASK, c);

        unsigned long long v = best[i];
#pragma unroll
        for (int off = 16; off; off >>= 1) {
            unsigned long long o = __shfl_down_sync(FULL_MASK, v, off);
            if (o > v) v = o;
        }
        if (lane == 0) {
            if (tot) atomicAdd(&d_cnt[base + i], tot);
            atomicMax(&d_key[base + i], v);
        }
    }
}

// ---------------- kernel 2: masked channel sums (predicated f32x2 adds) ------
// 768 blocks x 256 threads. Each warp owns 4 channels as 2 packed pairs;
// each lane owns acc2[2 pairs][16 instances] (64 regs) and walks pixels as
// float4. Gate = 1 LOP3 + 1 ISETP; add = 2 predicated FADD2 (no multiplier
// materialization at all).
__global__ void __launch_bounds__(256, 2) k_accum(const float* __restrict__ f0,
                                                  const float* __restrict__ f1,
                                                  const float* __restrict__ f2,
                                                  const float* __restrict__ f3) {
    const int bx = blockIdx.x;
    int lvl, b, cg, pstart, iters, P, moff;
    const float* f;
    if (bx < 512)      { lvl = 0; int t = bx;       b = t >> 6; cg = (t >> 3) & 7; pstart = (t & 7) * 2048; iters = 16; P = 16384; moff = 0;     f = f0; }
    else if (bx < 640) { lvl = 1; int t = bx - 512; b = t >> 4; cg = (t >> 1) & 7; pstart = (t & 1) * 2048; iters = 16; P = 4096;  moff = 16384; f = f1; }
    else if (bx < 704) { lvl = 2; int t = bx - 640; b = t >> 3; cg = t & 7;        pstart = 0;              iters = 8;  P = 1024;  moff = 20480; f = f2; }
    else               { lvl = 3; int t = bx - 704; b = t >> 3; cg = t & 7;        pstart = 0;              iters = 2;  P = 256;   moff = 21504; f = f3; }

    const int warp = threadIdx.x >> 5;
    const int lane = threadIdx.x & 31;
    const int c0   = cg * 32 + warp * 4;

    const float4* fp   = reinterpret_cast<const float4*>(f + (size_t)(b * 256 + c0) * P);
    const int     Pq   = P >> 2;
    const uint2*  mp   = reinterpret_cast<const uint2*>(d_mask);
    const int     mbse = (b * MTOT + moff) >> 2;

    unsigned long long acc2[2][16];
#pragma unroll
    for (int j = 0; j < 2; ++j)
#pragma unroll
        for (int i = 0; i < 16; ++i) acc2[j][i] = 0ull;

    for (int it = 0; it < iters; ++it) {
        const int q = (pstart + it * 128 + lane * 4) >> 2;

        uint2  mv = mp[mbse + q];
        float4 v0 = fp[q];
        float4 v1 = fp[Pq + q];
        float4 v2 = fp[2 * Pq + q];
        float4 v3 = fp[3 * Pq + q];

        const float* pv0 = reinterpret_cast<const float*>(&v0);
        const float* pv1 = reinterpret_cast<const float*>(&v1);
        const float* pv2 = reinterpret_cast<const float*>(&v2);
        const float* pv3 = reinterpret_cast<const float*>(&v3);

#pragma unroll
        for (int px = 0; px < 4; ++px) {
            const unsigned m16 = ((px & 2) ? mv.y : mv.x) >> ((px & 1) * 16);
            unsigned long long a01, a23;
            asm("mov.b64 %0, {%1, %2};" : "=l"(a01) : "f"(pv0[px]), "f"(pv1[px]));
            asm("mov.b64 %0, {%1, %2};" : "=l"(a23) : "f"(pv2[px]), "f"(pv3[px]));
#pragma unroll
            for (int i = 0; i < 16; ++i) {
                const unsigned bsel = m16 & (1u << i);   // LOP3 w/ immediate
                asm volatile(
                    "{ .reg .pred p;\n\t"
                    "  setp.ne.u32 p, %4, 0;\n\t"
                    "  @p add.rn.f32x2 %0, %0, %2;\n\t"
                    "  @p add.rn.f32x2 %1, %1, %3;\n\t}"
                    : "+l"(acc2[0][i]), "+l"(acc2[1][i])
                    : "l"(a01), "l"(a23), "r"(bsel));
            }
        }
    }

    // lane reduction on packed pairs + two atomics per (pair, instance)
    const int sb = lvl * 32768 + b * 4096;
#pragma unroll
    for (int j = 0; j < 2; ++j) {
#pragma unroll
        for (int i = 0; i < 16; ++i) {
            unsigned long long v = acc2[j][i];
#pragma unroll
            for (int off = 16; off; off >>= 1) {
                unsigned long long o = __shfl_down_sync(FULL_MASK, v, off);
                unsigned long long rr;
                ADD2(rr, v, o);
                v = rr;
            }
            if (lane == 0) {
                unsigned lo32, hi32;
                asm("mov.b64 {%0, %1}, %2;" : "=r"(lo32), "=r"(hi32) : "l"(v));
                atomicAdd(&d_s[sb + i * 256 + c0 + 2 * j],     __uint_as_float(lo32));
                atomicAdd(&d_s[sb + i * 256 + c0 + 2 * j + 1], __uint_as_float(hi32));
            }
        }
    }
}

// ---------------- kernel 3: finalize ----------------
// one block per (b, i); cnt/key staged through smem (block-uniform).
__global__ void __launch_bounds__(256) k_final(const float* __restrict__ f0,
                                               const float* __restrict__ f1,
                                               const float* __restrict__ f2,
                                               const float* __restrict__ f3,
                                               float* __restrict__ out) {
    const int bi = blockIdx.x;      // b*16 + i, 128 blocks
    const int c  = threadIdx.x;     // 256
    const int b  = bi >> 4;

    __shared__ int      scnt[4];
    __shared__ unsigned spix[4];
    if (c < 4) {
        const int idx = c * 128 + bi;
        scnt[c] = d_cnt[idx];
        spix[c] = 0xFFFFFFFFu - (unsigned)(d_key[idx] & 0xFFFFFFFFull);
    }
    __syncthreads();

    const float* fs[4] = { f0, f1, f2, f3 };
    const int    Ps[4] = { 16384, 4096, 1024, 256 };

    float sum = 0.0f;
#pragma unroll
    for (int l = 0; l < 4; ++l) {
        float v;
        if (scnt[l] > 0) {
            v = d_s[l * 32768 + bi * 256 + c] / (float)scnt[l];
        } else {
            v = fs[l][(size_t)(b * 256 + c) * Ps[l] + spix[l]];
        }
        sum += v;
    }
    out[bi * 256 + c] = sum * 0.25f;
}

// ---------------- launcher ----------------
extern "C" void kernel_launch(void* const* d_in, const int* in_sizes, int n_in,
                              void* d_out, int out_size) {
    const float* f0  = (const float*)d_in[0];
    const float* f1  = (const float*)d_in[1];
    const float* f2  = (const float*)d_in[2];
    const float* f3  = (const float*)d_in[3];
    const float* scr = (const float*)d_in[4];
    float* out = (float*)d_out;

    k_init<<<512, 256>>>();
    k_mask<<<170, 256>>>(scr);
    k_accum<<<768, 256>>>(f0, f1, f2, f3);
    k_final<<<128, 256>>>(f0, f1, f2, f3, out);
}

// round 4
// speedup vs baseline: 1.0600x; 1.0600x over previous
#include <cuda_runtime.h>
#include <cstdint>

#define FULL_MASK 0xFFFFFFFFu

// ---------------- problem constants ----------------
// B=8, I=16, C=256
// levels: H/W = 128,64,32,16 ; P = 16384,4096,1024,256
// scribbles: (8,16,512,512)
// resize: scale S={4,8,16,32}; both bilinear weights exactly 0.5, taps at
// S/2-1 and S/2 in each dim  -> first tap offset so={1,3,7,15}
#define MTOT 21760   // 16384+4096+1024+256 pixels per batch across levels

// ---------------- scratch (device globals; no allocation) ----------------
static __device__ float               d_s[4 * 8 * 16 * 256];     // per-level sums
static __device__ int                 d_cnt[4 * 8 * 16];         // per-level fg counts
static __device__ unsigned long long  d_key[4 * 8 * 16];         // argmax keys
static __device__ unsigned long long  d_mask[(8 * MTOT) / 4];    // bit-packed masks (uint16/pixel)

// packed f32x2 fma: d = a*b + d  (two independent fp32 FMAs, 1 instruction)
#define FFMA2(d, a, b) \
    asm("fma.rn.f32x2 %0, %1, %2, %0;" : "+l"(d) : "l"(a), "l"(b))
#define ADD2(d, a, b) \
    asm("add.rn.f32x2 %0, %1, %2;" : "=l"(d) : "l"(a), "l"(b))

// ---------------- kernel 0: zero scratch ----------------
__global__ void k_init() {
    int g = blockIdx.x * 256 + threadIdx.x;
    if (g < 4 * 8 * 16 * 256) d_s[g] = 0.0f;
    if (g < 4 * 8 * 16) { d_cnt[g] = 0; d_key[g] = 0ull; }
}

// ---------------- kernel 1: masks + counts + argmax ----------------
// 170 blocks x 256 threads. Each warp handles one 256-pixel tile for HALF of
// the 16 instances (8 each), writing its byte of the uint16 mask word.
__global__ void __launch_bounds__(256) k_mask(const float* __restrict__ scr) {
    const int warp = threadIdx.x >> 5;
    const int lane = threadIdx.x & 31;
    const int gw   = blockIdx.x * 8 + warp;   // 0..1359
    const int tile = gw >> 1;                 // 0..679
    const int ih   = gw & 1;                  // instance half (0: i0-7, 1: i8-15)
    const int wb   = tile * 256;              // global pixel base

    const int b = wb / MTOT;
    const int r = wb - b * MTOT;

    int lvl, loff, lw, ls, so;
    if (r < 16384)      { lvl = 0; loff = 0;     lw = 7; ls = 2; so = 1;  }
    else if (r < 20480) { lvl = 1; loff = 16384; lw = 6; ls = 3; so = 3;  }
    else if (r < 21504) { lvl = 2; loff = 20480; lw = 5; ls = 4; so = 7;  }
    else                { lvl = 3; loff = 21504; lw = 4; ls = 5; so = 15; }

    const int p0 = r - loff;
    const float* sbase = scr + (size_t)(b * 16 + ih * 8) * 262144;

    unsigned long long best[8];
#pragma unroll
    for (int i = 0; i < 8; ++i) best[i] = 0ull;
    unsigned cpack = 0u;  // 8 x 4-bit counters (max 8 each)

    unsigned char* mb = reinterpret_cast<unsigned char*>(d_mask);

#pragma unroll
    for (int k = 0; k < 8; ++k) {
        const int p  = p0 + k * 32 + lane;
        const int y  = p >> lw;
        const int x  = p & ((1 << lw) - 1);
        unsigned mask = 0u;

        if (lvl == 0) {
            // taps 4x+1, 4x+2 both live in aligned float4[x] of rows 4y+1, 4y+2
            const float* rp = sbase + (((y << 2) + 1) * 512 + (x << 2));
#pragma unroll
            for (int i = 0; i < 8; ++i) {
                const float4 q0 = *reinterpret_cast<const float4*>(rp + i * 262144);
                const float4 q1 = *reinterpret_cast<const float4*>(rp + i * 262144 + 512);
                float t0 = 0.5f * (q0.y + q1.y);
                float t1 = 0.5f * (q0.z + q1.z);
                float m  = 0.5f * (t0 + t1);

                unsigned bit = (m > 0.5f) ? 1u : 0u;
                mask  |= bit << i;
                cpack += bit << (4 * i);

                unsigned long long key =
                    ((unsigned long long)__float_as_uint(m) << 32) |
                    (unsigned long long)(0xFFFFFFFFu - (unsigned)p);
                if (key > best[i]) best[i] = key;
            }
        } else {
            const int y0 = (y << ls) + so;
            const int x0 = (x << ls) + so;
            const float* sp0 = sbase + y0 * 512 + x0;
#pragma unroll
            for (int i = 0; i < 8; ++i) {
                const float* sp = sp0 + i * 262144;
                float va = sp[0];
                float vb = sp[1];
                float vc = sp[512];
                float vd = sp[513];
                float t0 = 0.5f * (va + vc);
                float t1 = 0.5f * (vb + vd);
                float m  = 0.5f * (t0 + t1);

                unsigned bit = (m > 0.5f) ? 1u : 0u;
                mask  |= bit << i;
                cpack += bit << (4 * i);

                unsigned long long key =
                    ((unsigned long long)__float_as_uint(m) << 32) |
                    (unsigned long long)(0xFFFFFFFFu - (unsigned)p);
                if (key > best[i]) best[i] = key;
            }
        }
        mb[2 * (wb + k * 32 + lane) + ih] = (unsigned char)mask;
    }

    const int base = (lvl * 8 + b) * 16 + ih * 8;
#pragma unroll
    for (int i = 0; i < 8; ++i) {
        int c   = (int)((cpack >> (4 * i)) & 15u);
        int tot = __reduce_add_sync(FULL_MASK, c);

        unsigned long long v = best[i];
#pragma unroll
        for (int off = 16; off; off >>= 1) {
            unsigned long long o = __shfl_down_sync(FULL_MASK, v, off);
            if (o > v) v = o;
        }
        if (lane == 0) {
            if (tot) atomicAdd(&d_cnt[base + i], tot);
            atomicMax(&d_key[base + i], v);
        }
    }
}

// ---------------- kernel 2: masked channel sums (packed f32x2) ----------------
// 768 blocks x 256 threads. Each warp owns 4 channels as 2 packed pairs;
// each lane owns acc2[2 pairs][16 instances] and walks pixels as float4.
// NOTE: no forced min-blocks-per-SM — let ptxas pick natural register count
// (forced 128-reg cap was the suspected spill source).
__global__ void __launch_bounds__(256) k_accum(const float* __restrict__ f0,
                                               const float* __restrict__ f1,
                                               const float* __restrict__ f2,
                                               const float* __restrict__ f3) {
    const int bx = blockIdx.x;
    int lvl, b, cg, pstart, iters, P, moff;
    const float* f;
    if (bx < 512)      { lvl = 0; int t = bx;       b = t >> 6; cg = (t >> 3) & 7; pstart = (t & 7) * 2048; iters = 16; P = 16384; moff = 0;     f = f0; }
    else if (bx < 640) { lvl = 1; int t = bx - 512; b = t >> 4; cg = (t >> 1) & 7; pstart = (t & 1) * 2048; iters = 16; P = 4096;  moff = 16384; f = f1; }
    else if (bx < 704) { lvl = 2; int t = bx - 640; b = t >> 3; cg = t & 7;        pstart = 0;              iters = 8;  P = 1024;  moff = 20480; f = f2; }
    else               { lvl = 3; int t = bx - 704; b = t >> 3; cg = t & 7;        pstart = 0;              iters = 2;  P = 256;   moff = 21504; f = f3; }

    const int warp = threadIdx.x >> 5;
    const int lane = threadIdx.x & 31;
    const int c0   = cg * 32 + warp * 4;

    const float4* fp   = reinterpret_cast<const float4*>(f + (size_t)(b * 256 + c0) * P);
    const int     Pq   = P >> 2;
    const uint2*  mp   = reinterpret_cast<const uint2*>(d_mask);
    const int     mbse = (b * MTOT + moff) >> 2;

    unsigned long long acc2[2][16];
#pragma unroll
    for (int j = 0; j < 2; ++j)
#pragma unroll
        for (int i = 0; i < 16; ++i) acc2[j][i] = 0ull;

    for (int it = 0; it < iters; ++it) {
        const int q = (pstart + it * 128 + lane * 4) >> 2;

        uint2  mv = mp[mbse + q];
        float4 v0 = fp[q];
        float4 v1 = fp[Pq + q];
        float4 v2 = fp[2 * Pq + q];
        float4 v3 = fp[3 * Pq + q];

        const float* pv0 = reinterpret_cast<const float*>(&v0);
        const float* pv1 = reinterpret_cast<const float*>(&v1);
        const float* pv2 = reinterpret_cast<const float*>(&v2);
        const float* pv3 = reinterpret_cast<const float*>(&v3);

#pragma unroll
        for (int px = 0; px < 4; ++px) {
            const unsigned m16 = ((px & 2) ? mv.y : mv.x) >> ((px & 1) * 16);
            unsigned long long a01, a23;
            asm("mov.b64 %0, {%1, %2};" : "=l"(a01) : "f"(pv0[px]), "f"(pv1[px]));
            asm("mov.b64 %0, {%1, %2};" : "=l"(a23) : "f"(pv2[px]), "f"(pv3[px]));
#pragma unroll
            for (int i = 0; i < 16; ++i) {
                const unsigned fmu = ((m16 >> i) & 1u) * 0x3F800000u;
                unsigned long long fm2;
                asm("mov.b64 %0, {%1, %1};" : "=l"(fm2) : "r"(fmu));
                FFMA2(acc2[0][i], a01, fm2);
                FFMA2(acc2[1][i], a23, fm2);
            }
        }
    }

    // lane reduction on packed pairs + two atomics per (pair, instance)
    const int sb = lvl * 32768 + b * 4096;
#pragma unroll
    for (int j = 0; j < 2; ++j) {
#pragma unroll
        for (int i = 0; i < 16; ++i) {
            unsigned long long v = acc2[j][i];
#pragma unroll
            for (int off = 16; off; off >>= 1) {
                unsigned long long o = __shfl_down_sync(FULL_MASK, v, off);
                unsigned long long rr;
                ADD2(rr, v, o);
                v = rr;
            }
            if (lane == 0) {
                unsigned lo32, hi32;
                asm("mov.b64 {%0, %1}, %2;" : "=r"(lo32), "=r"(hi32) : "l"(v));
                atomicAdd(&d_s[sb + i * 256 + c0 + 2 * j],     __uint_as_float(lo32));
                atomicAdd(&d_s[sb + i * 256 + c0 + 2 * j + 1], __uint_as_float(hi32));
            }
        }
    }
}

// ---------------- kernel 3: finalize ----------------
// one block per (b, i); cnt/key staged through smem (block-uniform).
__global__ void __launch_bounds__(256) k_final(const float* __restrict__ f0,
                                               const float* __restrict__ f1,
                                               const float* __restrict__ f2,
                                               const float* __restrict__ f3,
                                               float* __restrict__ out) {
    const int bi = blockIdx.x;      // b*16 + i, 128 blocks
    const int c  = threadIdx.x;     // 256
    const int b  = bi >> 4;

    __shared__ int      scnt[4];
    __shared__ unsigned spix[4];
    if (c < 4) {
        const int idx = c * 128 + bi;
        scnt[c] = d_cnt[idx];
        spix[c] = 0xFFFFFFFFu - (unsigned)(d_key[idx] & 0xFFFFFFFFull);
    }
    __syncthreads();

    const float* fs[4] = { f0, f1, f2, f3 };
    const int    Ps[4] = { 16384, 4096, 1024, 256 };

    float sum = 0.0f;
#pragma unroll
    for (int l = 0; l < 4; ++l) {
        float v;
        if (scnt[l] > 0) {
            v = d_s[l * 32768 + bi * 256 + c] / (float)scnt[l];
        } else {
            v = fs[l][(size_t)(b * 256 + c) * Ps[l] + spix[l]];
        }
        sum += v;
    }
    out[bi * 256 + c] = sum * 0.25f;
}

// ---------------- launcher ----------------
extern "C" void kernel_launch(void* const* d_in, const int* in_sizes, int n_in,
                              void* d_out, int out_size) {
    const float* f0  = (const float*)d_in[0];
    const float* f1  = (const float*)d_in[1];
    const float* f2  = (const float*)d_in[2];
    const float* f3  = (const float*)d_in[3];
    const float* scr = (const float*)d_in[4];
    float* out = (float*)d_out;

    k_init<<<512, 256>>>();
    k_mask<<<170, 256>>>(scr);
    k_accum<<<768, 256>>>(f0, f1, f2, f3);
    k_final<<<128, 256>>>(f0, f1, f2, f3, out);
}